// round 15
// baseline (speedup 1.0000x reference)
#include <cuda_runtime.h>
#include <cuda_fp16.h>
#include <cstdint>
#include <math.h>

typedef __half f16;

#define BDIM 48
#define HDIM 56
#define WDIM 56
#define CDIM 256
#define TDIM 3
#define NTOK 50176        /* (B/T)*H*W */
#define MROWS 150528      /* NTOK*T = B*H*W */
#define HID 1024
#define EPSLN 1e-6f

// ---------------- scratch (static device allocations) ----------------
__device__ f16   g_xn  [(size_t)MROWS*CDIM];
__device__ f16   g_attn[(size_t)MROWS*CDIM];
__device__ f16   g_xt16[(size_t)MROWS*CDIM];   /* xt = proj_out + bias + x, fp16 */
__device__ f16   g_xtn [(size_t)MROWS*CDIM];
__device__ f16   g_h   [(size_t)MROWS*HID];
__device__ f16   g_wkvq[3*CDIM*CDIM];          /* head-grouped permuted rows */
__device__ float g_bkvq[3*CDIM];               /* permuted kvq bias */
__device__ f16   g_wproj[CDIM*CDIM];
__device__ f16   g_wfc1[HID*CDIM];
__device__ f16   g_wfc2[CDIM*HID];

// ---------------- small helpers ----------------
__device__ __forceinline__ uint32_t pack_h2(float a, float b) {
    __half2 h = __floats2half2_rn(a, b);
    return *reinterpret_cast<uint32_t*>(&h);
}
__device__ __forceinline__ float2 unpack_h2(uint32_t u) {
    return __half22float2(*reinterpret_cast<__half2*>(&u));
}
__device__ __forceinline__ uint32_t s2u(const void* p) {
    uint32_t a;
    asm("{ .reg .u64 t; cvta.to.shared.u64 t, %1; cvt.u32.u64 %0, t; }" : "=r"(a) : "l"(p));
    return a;
}
#define CP_ASYNC16(saddr, gptr) \
    asm volatile("cp.async.cg.shared.global [%0], [%1], 16;" :: "r"(saddr), "l"(gptr) : "memory")
#define CP_COMMIT() asm volatile("cp.async.commit_group;" ::: "memory")

#define LDSM_X4(r0, r1, r2, r3, a) \
    asm volatile("ldmatrix.sync.aligned.m8n8.x4.shared.b16 {%0,%1,%2,%3}, [%4];" \
        : "=r"(r0), "=r"(r1), "=r"(r2), "=r"(r3) : "r"(a))

#define HMMA_F16(acc, a0, a1, a2, a3, b0, b1) \
    asm volatile( \
        "mma.sync.aligned.m16n8k16.row.col.f16.f16.f16.f16 " \
        "{%0,%1}, {%2,%3,%4,%5}, {%6,%7}, {%0,%1};\n" \
        : "+r"((acc)[0]), "+r"((acc)[1]) \
        : "r"(a0), "r"(a1), "r"(a2), "r"(a3), "r"(b0), "r"(b1))

// ---------------- LN1 + weight conversion (merged, grid-partitioned) ----------
#define LN1_BLOCKS (MROWS / 8)       /* 18816 */
#define CONV_BLOCKS 1024

__device__ __forceinline__ void warpLN8(float* v, float& mu, float& rstd) {
    float s = 0.f, s2 = 0.f;
    #pragma unroll
    for (int j = 0; j < 8; j++) { s += v[j]; s2 += v[j] * v[j]; }
    #pragma unroll
    for (int o = 16; o; o >>= 1) {
        s  += __shfl_xor_sync(0xffffffffu, s,  o);
        s2 += __shfl_xor_sync(0xffffffffu, s2, o);
    }
    mu = s * (1.f / CDIM);
    rstd = rsqrtf(s2 * (1.f / CDIM) - mu * mu + EPSLN);
}

__global__ void prep_kernel(const float* __restrict__ x, const float* __restrict__ w,
                            const float* __restrict__ b,
                            const float* __restrict__ wkvq, const float* __restrict__ kvq_b,
                            const float* __restrict__ wproj,
                            const float* __restrict__ wfc1, const float* __restrict__ wfc2) {
    if (blockIdx.x >= LN1_BLOCKS) {
        int i = (blockIdx.x - LN1_BLOCKS) * 256 + threadIdx.x;
        if (i < 3*CDIM*CDIM) {
            int rp = i >> 8, k = i & 255;
            int h = rp / 96, j = rp - h * 96;
            int orig = (j < 32) ? (h*32 + j) : (j < 64) ? (256 + h*32 + j - 32) : (512 + h*32 + j - 64);
            g_wkvq[i] = __float2half(wkvq[orig * 256 + k]);
            if (i < 768) {
                int hh = i / 96, jj = i - hh * 96;
                int ob = (jj < 32) ? (hh*32 + jj) : (jj < 64) ? (256 + hh*32 + jj - 32) : (512 + hh*32 + jj - 64);
                g_bkvq[i] = kvq_b[ob];
            }
        }
        if (i < CDIM*CDIM)   g_wproj[i] = __float2half(wproj[i]);
        if (i < HID*CDIM) {
            g_wfc1[i] = __float2half(wfc1[i]);
            g_wfc2[i] = __float2half(wfc2[i]);
        }
        return;
    }
    int r = blockIdx.x * 8 + (threadIdx.x >> 5);
    int lane = threadIdx.x & 31;
    const float4* px = (const float4*)(x + (size_t)r * CDIM);
    float4 a0 = px[lane * 2], a1 = px[lane * 2 + 1];
    float v[8] = {a0.x, a0.y, a0.z, a0.w, a1.x, a1.y, a1.z, a1.w};
    float mu, rstd;
    warpLN8(v, mu, rstd);
    float4 w0 = ((const float4*)w)[lane*2], w1 = ((const float4*)w)[lane*2+1];
    float4 b0 = ((const float4*)b)[lane*2], b1 = ((const float4*)b)[lane*2+1];
    float wv[8] = {w0.x,w0.y,w0.z,w0.w,w1.x,w1.y,w1.z,w1.w};
    float bv[8] = {b0.x,b0.y,b0.z,b0.w,b1.x,b1.y,b1.z,b1.w};
    uint32_t o[4];
    #pragma unroll
    for (int j = 0; j < 4; j++) {
        float y0 = (v[2*j]   - mu) * rstd * wv[2*j]   + bv[2*j];
        float y1 = (v[2*j+1] - mu) * rstd * wv[2*j+1] + bv[2*j+1];
        o[j] = pack_h2(y0, y1);
    }
    int ww = r % WDIM; int r2 = r / WDIM;
    int hh = r2 % HDIM; int bb = r2 / HDIM;
    int bh = bb / TDIM, t = bb - bh * TDIM;
    int m = ((bh * HDIM + hh) * WDIM + ww) * TDIM + t;
    ((uint4*)(g_xn + (size_t)m * CDIM))[lane] = make_uint4(o[0], o[1], o[2], o[3]);
}

// ======= fused kvq GEMM + attention: 192x96 tile, 3-stage ring, 3 CTAs/SM =======
#define KBM 192
#define KBN 96
#define BKK 32
#define LDSS 40
#define KS3 3
#define KA_BYTES (KBM * LDSS * 2)      /* 15360 */
#define KB_BYTES (KBN * LDSS * 2)      /* 7680  */
#define KSTAGE (KA_BYTES + KB_BYTES)   /* 23040 */
#define KV_SMEM (KS3 * KSTAGE)         /* 69120 */
#define ATTP 104                        /* attention smem pitch (halves) */

__global__ void __launch_bounds__(256, 3) kvqattn_kernel() {
    constexpr int NKT = CDIM / BKK;    // 8
    extern __shared__ char dsm[];
    const uint32_t p0 = s2u(dsm);

    const int bn = blockIdx.x, bm = blockIdx.y;   // bn = head
    const int tid = threadIdx.x;
    const int warp = tid >> 5, lane = tid & 31;
    const int wm = warp & 3, wn = warp >> 2;      // 4(m) x 2(n); warp tile 48x48
    const int gro = lane >> 2, thr = lane & 3;
    const size_t aBase = (size_t)bm * KBM * CDIM;
    const size_t bBase = (size_t)bn * KBN * CDIM;

    const int aRow = wm * 48 + (lane & 7) + ((lane >> 3) & 1) * 8;  // + mi*16
    const int aCol = (lane >> 4) * 8;
    const int bRow = wn * 48 + (lane & 7) + (lane >> 4) * 8;        // + pr*16
    const int bCol = ((lane >> 3) & 1) * 8;

    auto loadTile = [&](int st, int kt) {
        int k0 = kt * BKK;
        uint32_t base = p0 + st * KSTAGE;
        #pragma unroll
        for (int i = 0; i < 3; i++) {          // A: 192x4 = 768 chunks
            int idx = tid + i * 256;
            int row = idx >> 2, ch = idx & 3;
            CP_ASYNC16(base + (uint32_t)((row * LDSS + ch * 8) * 2),
                       g_xn + aBase + (size_t)row * CDIM + k0 + ch * 8);
        }
        {                                       // B: 96x4 = 384 chunks
            uint32_t bB = base + KA_BYTES;
            int row = tid >> 2, ch = tid & 3;
            CP_ASYNC16(bB + (uint32_t)((row * LDSS + ch * 8) * 2),
                       g_wkvq + bBase + (size_t)row * CDIM + k0 + ch * 8);
            if (tid < 128) {
                int idx = 256 + tid;
                int r2 = idx >> 2, c2 = idx & 3;
                CP_ASYNC16(bB + (uint32_t)((r2 * LDSS + c2 * 8) * 2),
                           g_wkvq + bBase + (size_t)r2 * CDIM + k0 + c2 * 8);
            }
        }
        CP_COMMIT();
    };

    uint32_t acch[3][6][2];
    #pragma unroll
    for (int i = 0; i < 3; i++)
        #pragma unroll
        for (int j = 0; j < 6; j++) { acch[i][j][0] = 0u; acch[i][j][1] = 0u; }

    loadTile(0, 0);
    loadTile(1, 1);
    for (int kt = 0; kt < NKT; kt++) {
        if (kt < NKT - 1) asm volatile("cp.async.wait_group 1;" ::: "memory");
        else              asm volatile("cp.async.wait_group 0;" ::: "memory");
        __syncthreads();
        if (kt + 2 < NKT) loadTile((kt + 2) % KS3, kt + 2);
        const int st = kt % KS3;
        uint32_t base = p0 + st * KSTAGE;
        #pragma unroll
        for (int ks = 0; ks < 2; ks++) {
            uint32_t af[3][4];
            #pragma unroll
            for (int mi = 0; mi < 3; mi++) {
                uint32_t addr = base +
                    (uint32_t)(((aRow + mi * 16) * LDSS + ks * 16 + aCol) * 2);
                LDSM_X4(af[mi][0], af[mi][1], af[mi][2], af[mi][3], addr);
            }
            uint32_t bfr[6][2];
            #pragma unroll
            for (int pr = 0; pr < 3; pr++) {
                uint32_t addr = base + KA_BYTES +
                    (uint32_t)(((bRow + pr * 16) * LDSS + ks * 16 + bCol) * 2);
                LDSM_X4(bfr[pr*2][0], bfr[pr*2][1], bfr[pr*2+1][0], bfr[pr*2+1][1], addr);
            }
            #pragma unroll
            for (int ni = 0; ni < 6; ni++)
                #pragma unroll
                for (int mi = 0; mi < 3; mi++)
                    HMMA_F16(acch[mi][ni], af[mi][0], af[mi][1], af[mi][2], af[mi][3],
                             bfr[ni][0], bfr[ni][1]);
        }
    }

    // ---- epilogue 1: biased kvq tile -> smem (192 rows x 96 cols, pitch 104) ----
    __syncthreads();   // all MMAs done reading pipeline smem
    f16* att = (f16*)dsm;
    #pragma unroll
    for (int mi = 0; mi < 3; mi++) {
        #pragma unroll
        for (int rr = 0; rr < 2; rr++) {
            int row = wm * 48 + mi * 16 + rr * 8 + gro;
            #pragma unroll
            for (int ni = 0; ni < 6; ni++) {
                int j = wn * 48 + ni * 8 + thr * 2;
                float2 d = unpack_h2(acch[mi][ni][rr]);
                float2 bb = *(const float2*)&g_bkvq[bn * 96 + j];
                *(uint32_t*)&att[row * ATTP + j] = pack_h2(d.x + bb.x, d.y + bb.y);
            }
        }
    }
    __syncthreads();

    // ---- epilogue 2: attention; 4 threads per n-group, 8 d-channels each ----
    {
        int g = tid >> 2, qd = tid & 3;       // 64 groups, quarter qd
        const f16* rbase = att + (3 * g) * ATTP + qd * 8;
        float2 kv[3][4], qv[3][4];
        #pragma unroll
        for (int t = 0; t < 3; t++) {
            uint4 uk = *(const uint4*)(rbase + t * ATTP +  0);
            uint4 uq = *(const uint4*)(rbase + t * ATTP + 64);
            kv[t][0] = unpack_h2(uk.x); kv[t][1] = unpack_h2(uk.y);
            kv[t][2] = unpack_h2(uk.z); kv[t][3] = unpack_h2(uk.w);
            qv[t][0] = unpack_h2(uq.x); qv[t][1] = unpack_h2(uq.y);
            qv[t][2] = unpack_h2(uq.z); qv[t][3] = unpack_h2(uq.w);
        }
        float dot[3][3];
        #pragma unroll
        for (int a = 0; a < 3; a++)
            #pragma unroll
            for (int s = 0; s < 3; s++) {
                float p = 0.f;
                #pragma unroll
                for (int j = 0; j < 4; j++)
                    p += qv[a][j].x * kv[s][j].x + qv[a][j].y * kv[s][j].y;
                dot[a][s] = p;
            }
        #pragma unroll
        for (int a = 0; a < 3; a++)
            #pragma unroll
            for (int s = 0; s < 3; s++) {
                dot[a][s] += __shfl_xor_sync(0xffffffffu, dot[a][s], 1);
                dot[a][s] += __shfl_xor_sync(0xffffffffu, dot[a][s], 2);
            }
        float wgt[3][3];
        #pragma unroll
        for (int a = 0; a < 3; a++) {
            float l0 = dot[a][0] * 0.17677669529663687f;
            float l1 = dot[a][1] * 0.17677669529663687f;
            float l2 = dot[a][2] * 0.17677669529663687f;
            float mx = fmaxf(l0, fmaxf(l1, l2));
            float e0 = __expf(l0 - mx), e1 = __expf(l1 - mx), e2 = __expf(l2 - mx);
            float inv = 1.f / (e0 + e1 + e2);
            wgt[a][0] = e0 * inv; wgt[a][1] = e1 * inv; wgt[a][2] = e2 * inv;
        }
        float2 vv[3][4];
        #pragma unroll
        for (int t = 0; t < 3; t++) {
            uint4 uv = *(const uint4*)(rbase + t * ATTP + 32);
            vv[t][0] = unpack_h2(uv.x); vv[t][1] = unpack_h2(uv.y);
            vv[t][2] = unpack_h2(uv.z); vv[t][3] = unpack_h2(uv.w);
        }
        int n = bm * 64 + g;
        #pragma unroll
        for (int a = 0; a < 3; a++) {
            uint32_t o[4];
            #pragma unroll
            for (int j = 0; j < 4; j++) {
                float ox = wgt[a][0]*vv[0][j].x + wgt[a][1]*vv[1][j].x + wgt[a][2]*vv[2][j].x;
                float oy = wgt[a][0]*vv[0][j].y + wgt[a][1]*vv[1][j].y + wgt[a][2]*vv[2][j].y;
                o[j] = pack_h2(ox, oy);
            }
            *(uint4*)(g_attn + (size_t)(n*3 + a) * CDIM + bn*32 + qd*8) =
                make_uint4(o[0], o[1], o[2], o[3]);
        }
    }
}

// ====== main GEMM: 128x128 tile, 3-stage ring, 3 CTAs/SM ======
#define BM 128
#define BN 128
#define GS 3
#define STAGE_BYTES (BM * LDSS * 2)                 /* 10240 */
#define GEMM_SMEM (GS * 2 * STAGE_BYTES)            /* 61440 */

// EPI: 2 = fc1 (f16 acc, bias + gelu -> f16 g_h)
//      3 = fc2 (f16 acc, bias + xt16 residual -> fp32 out, scattered)
template<int EPI, int NDIM, int KDIM>
__global__ void __launch_bounds__(256, 3) gemm_kernel(const float* __restrict__ bias,
                                                      float* __restrict__ gout) {
    constexpr int NKT = KDIM / BKK;
    const f16 *A, *W;
    if constexpr (EPI == 2) { A = g_xtn; W = g_wfc1; }
    else                    { A = g_h;   W = g_wfc2; }

    extern __shared__ char dsm[];
    const uint32_t sA0 = s2u(dsm);
    const uint32_t sB0 = sA0 + GS * STAGE_BYTES;

    const int bn = blockIdx.x, bm = blockIdx.y;
    const int tid = threadIdx.x;
    const int warp = tid >> 5, lane = tid & 31;
    const int wm = warp & 3, wn = warp >> 2;
    const int gro = lane >> 2, thr = lane & 3;
    const size_t aBase = (size_t)bm * BM * KDIM;
    const size_t bBase = (size_t)bn * BN * KDIM;

    const int aRow = wm * 32 + (lane & 7) + ((lane >> 3) & 1) * 8;
    const int aCol = (lane >> 4) * 8;
    const int bRow = wn * 64 + (lane & 7) + (lane >> 4) * 8;
    const int bCol = ((lane >> 3) & 1) * 8;

    const int lrow = tid >> 2, lch = tid & 3;
    auto loadTile = [&](int st, int kt) {
        int k0 = kt * BKK;
        uint32_t dA = sA0 + st * STAGE_BYTES + (uint32_t)((lrow * LDSS + lch * 8) * 2);
        uint32_t dB = sB0 + st * STAGE_BYTES + (uint32_t)((lrow * LDSS + lch * 8) * 2);
        const f16* ga = A + aBase + (size_t)lrow * KDIM + k0 + lch * 8;
        const f16* gb = W + bBase + (size_t)lrow * KDIM + k0 + lch * 8;
        CP_ASYNC16(dA, ga);
        CP_ASYNC16(dA + (uint32_t)(64 * LDSS * 2), ga + (size_t)64 * KDIM);
        CP_ASYNC16(dB, gb);
        CP_ASYNC16(dB + (uint32_t)(64 * LDSS * 2), gb + (size_t)64 * KDIM);
        CP_COMMIT();
    };

    uint32_t acch[2][8][2];
    #pragma unroll
    for (int i = 0; i < 2; i++)
        #pragma unroll
        for (int j = 0; j < 8; j++) { acch[i][j][0] = 0u; acch[i][j][1] = 0u; }

    loadTile(0, 0);
    loadTile(1, 1);
    for (int kt = 0; kt < NKT; kt++) {
        if (kt < NKT - 1) asm volatile("cp.async.wait_group 1;" ::: "memory");
        else              asm volatile("cp.async.wait_group 0;" ::: "memory");
        __syncthreads();
        if (kt + 2 < NKT) loadTile((kt + 2) % GS, kt + 2);
        const int st = kt % GS;
        #pragma unroll
        for (int ks = 0; ks < 2; ks++) {
            uint32_t af[2][4];
            #pragma unroll
            for (int mi = 0; mi < 2; mi++) {
                uint32_t addr = sA0 + st * STAGE_BYTES +
                    (uint32_t)(((aRow + mi * 16) * LDSS + ks * 16 + aCol) * 2);
                LDSM_X4(af[mi][0], af[mi][1], af[mi][2], af[mi][3], addr);
            }
            uint32_t bfr[8][2];
            #pragma unroll
            for (int pr = 0; pr < 4; pr++) {
                uint32_t addr = sB0 + st * STAGE_BYTES +
                    (uint32_t)(((bRow + pr * 16) * LDSS + ks * 16 + bCol) * 2);
                LDSM_X4(bfr[pr*2][0], bfr[pr*2][1], bfr[pr*2+1][0], bfr[pr*2+1][1], addr);
            }
            #pragma unroll
            for (int ni = 0; ni < 8; ni++)
                #pragma unroll
                for (int mi = 0; mi < 2; mi++)
                    HMMA_F16(acch[mi][ni], af[mi][0], af[mi][1], af[mi][2], af[mi][3],
                             bfr[ni][0], bfr[ni][1]);
        }
    }

    // ---- epilogue ----
    const int cb = bn * BN + wn * 64 + thr * 2;
    #pragma unroll
    for (int mi = 0; mi < 2; mi++) {
        #pragma unroll
        for (int rr = 0; rr < 2; rr++) {
            int m = bm * BM + wm * 32 + mi * 16 + rr * 8 + gro;
            size_t xidx = 0;
            if constexpr (EPI == 3) {
                int t = m % 3;
                int n = m / 3;
                int ww = n % WDIM;
                int r2 = n / WDIM;
                int hh = r2 % HDIM;
                int bhat = r2 / HDIM;
                int b = bhat * TDIM + t;
                xidx = ((size_t)((b * HDIM + hh) * WDIM + ww)) * CDIM;
            }
            #pragma unroll
            for (int ni = 0; ni < 8; ni++) {
                int c = cb + ni * 8;
                float2 d = unpack_h2(acch[mi][ni][rr]);
                float v0 = d.x + bias[c], v1 = d.y + bias[c + 1];
                if constexpr (EPI == 2) {
                    v0 = 0.5f * v0 * (1.f + erff(v0 * 0.7071067811865475f));
                    v1 = 0.5f * v1 * (1.f + erff(v1 * 0.7071067811865475f));
                    *(uint32_t*)&g_h[(size_t)m * NDIM + c] = pack_h2(v0, v1);
                } else {
                    float2 xt = unpack_h2(*(const uint32_t*)&g_xt16[(size_t)m * CDIM + c]);
                    *(float2*)&gout[xidx + c] = make_float2(v0 + xt.x, v1 + xt.y);
                }
            }
        }
    }
}

// ====== fused proj + residual + LN2: 128x256 tile, warp 64x64, 3-stage, f16 acc ======
#define PBM 128
#define PS 3
#define PA_BYTES (PBM * LDSS * 2)     /* 10240 */
#define PB_BYTES (CDIM * LDSS * 2)    /* 20480 */
#define PSTAGE (PA_BYTES + PB_BYTES)  /* 30720 */
#define PROJ_SMEM (PS * PSTAGE)       /* 92160 */

__global__ void __launch_bounds__(256, 2) projln_kernel(const float* __restrict__ bias,
                                                        const float* __restrict__ x,
                                                        const float* __restrict__ w2,
                                                        const float* __restrict__ b2) {
    constexpr int NKT = CDIM / BKK;   // 8
    extern __shared__ char dsm[];
    __shared__ float2 red[PBM][4];

    const uint32_t p0 = s2u(dsm);
    const int bm = blockIdx.x;
    const int tid = threadIdx.x;
    const int warp = tid >> 5, lane = tid & 31;
    const int wm = warp & 1, wn = warp >> 1;      // 2(m) x 4(n); warp tile 64x64
    const int gro = lane >> 2, thr = lane & 3;
    const size_t aBase = (size_t)bm * PBM * CDIM;

    const int aRow = wm * 64 + (lane & 7) + ((lane >> 3) & 1) * 8;   // + mi*16
    const int aCol = (lane >> 4) * 8;
    const int bRow = wn * 64 + (lane & 7) + (lane >> 4) * 8;         // + pr*16
    const int bCol = ((lane >> 3) & 1) * 8;

    auto loadTile = [&](int st, int kt) {
        int k0 = kt * BKK;
        uint32_t base = p0 + st * PSTAGE;
        #pragma unroll
        for (int i = 0; i < 2; i++) {    // A: 128x4 = 512 chunks, 2/thread
            int idx = tid + i * 256;
            int row = idx >> 2, ch = idx & 3;
            CP_ASYNC16(base + (uint32_t)((row * LDSS + ch * 8) * 2),
                       g_attn + aBase + (size_t)row * CDIM + k0 + ch * 8);
        }
        {
            uint32_t bB = base + PA_BYTES;
            #pragma unroll
            for (int i = 0; i < 4; i++) {   // B: 256x4 = 1024 chunks, 4/thread
                int idx = tid + i * 256;
                int row = idx >> 2, ch = idx & 3;
                CP_ASYNC16(bB + (uint32_t)((row * LDSS + ch * 8) * 2),
                           g_wproj + (size_t)row * CDIM + k0 + ch * 8);
            }
        }
        CP_COMMIT();
    };

    uint32_t acch[4][8][2];
    #pragma unroll
    for (int i = 0; i < 4; i++)
        #pragma unroll
        for (int j = 0; j < 8; j++) { acch[i][j][0] = 0u; acch[i][j][1] = 0u; }

    loadTile(0, 0);
    loadTile(1, 1);
    for (int kt = 0; kt < NKT; kt++) {
        if (kt < NKT - 1) asm volatile("cp.async.wait_group 1;" ::: "memory");
        else              asm volatile("cp.async.wait_group 0;" ::: "memory");
        __syncthreads();
        if (kt + 2 < NKT) loadTile((kt + 2) % PS, kt + 2);
        const int st = kt % PS;
        uint32_t base = p0 + st * PSTAGE;
        #pragma unroll
        for (int ks = 0; ks < 2; ks++) {
            uint32_t af[4][4];
            #pragma unroll
            for (int mi = 0; mi < 4; mi++) {
                uint32_t addr = base +
                    (uint32_t)(((aRow + mi * 16) * LDSS + ks * 16 + aCol) * 2);
                LDSM_X4(af[mi][0], af[mi][1], af[mi][2], af[mi][3], addr);
            }
            uint32_t bfr[8][2];
            #pragma unroll
            for (int pr = 0; pr < 4; pr++) {
                uint32_t addr = base + PA_BYTES +
                    (uint32_t)(((bRow + pr * 16) * LDSS + ks * 16 + bCol) * 2);
                LDSM_X4(bfr[pr*2][0], bfr[pr*2][1], bfr[pr*2+1][0], bfr[pr*2+1][1], addr);
            }
            #pragma unroll
            for (int ni = 0; ni < 8; ni++)
                #pragma unroll
                for (int mi = 0; mi < 4; mi++)
                    HMMA_F16(acch[mi][ni], af[mi][0], af[mi][1], af[mi][2], af[mi][3],
                             bfr[ni][0], bfr[ni][1]);
        }
    }

    // ---- epilogue pass 1: bias + x -> xt (f16 gmem + regs); row stats ----
    #pragma unroll
    for (int mi = 0; mi < 4; mi++) {
        #pragma unroll
        for (int rr = 0; rr < 2; rr++) {
            int ml = wm * 64 + mi * 16 + rr * 8 + gro;
            int m = bm * PBM + ml;
            int t = m % 3;
            int n = m / 3;
            int ww = n % WDIM;
            int r2 = n / WDIM;
            int hh = r2 % HDIM;
            int bhat = r2 / HDIM;
            const float* xrow = x + ((size_t)(((bhat * TDIM + t) * HDIM + hh) * WDIM + ww)) * CDIM;

            float s = 0.f, s2 = 0.f;
            #pragma unroll
            for (int ni = 0; ni < 8; ni++) {
                int c = wn * 64 + ni * 8 + thr * 2;
                float2 d = unpack_h2(acch[mi][ni][rr]);
                float2 bb = *(const float2*)&bias[c];
                float2 xx = *(const float2*)&xrow[c];
                float v0 = d.x + bb.x + xx.x;
                float v1 = d.y + bb.y + xx.y;
                uint32_t pk = pack_h2(v0, v1);
                *(uint32_t*)&g_xt16[(size_t)m * CDIM + c] = pk;
                acch[mi][ni][rr] = pk;                 // xt stays in regs
                s += v0 + v1; s2 += v0*v0 + v1*v1;
            }
            #pragma unroll
            for (int o = 1; o < 4; o <<= 1) {
                s  += __shfl_xor_sync(0xffffffffu, s,  o);
                s2 += __shfl_xor_sync(0xffffffffu, s2, o);
            }
            if (thr == 0) red[ml][wn] = make_float2(s, s2);
        }
    }
    __syncthreads();

    // ---- epilogue pass 2: normalize from regs -> g_xtn ----
    #pragma unroll
    for (int mi = 0; mi < 4; mi++) {
        #pragma unroll
        for (int rr = 0; rr < 2; rr++) {
            int ml = wm * 64 + mi * 16 + rr * 8 + gro;
            int m = bm * PBM + ml;
            float2 r0 = red[ml][0], r1 = red[ml][1], r2v = red[ml][2], r3 = red[ml][3];
            float mu = (r0.x + r1.x + r2v.x + r3.x) * (1.f / CDIM);
            float var = (r0.y + r1.y + r2v.y + r3.y) * (1.f / CDIM) - mu * mu;
            float rstd = rsqrtf(var + EPSLN);
            #pragma unroll
            for (int ni = 0; ni < 8; ni++) {
                int c = wn * 64 + ni * 8 + thr * 2;
                float2 vt = unpack_h2(acch[mi][ni][rr]);
                float2 ww2 = *(const float2*)&w2[c];
                float2 bb2 = *(const float2*)&b2[c];
                float y0 = (vt.x - mu) * rstd * ww2.x + bb2.x;
                float y1 = (vt.y - mu) * rstd * ww2.y + bb2.y;
                *(uint32_t*)&g_xtn[(size_t)m * CDIM + c] = pack_h2(y0, y1);
            }
        }
    }
}

// ---------------- launch ----------------
extern "C" void kernel_launch(void* const* d_in, const int* in_sizes, int n_in,
                              void* d_out, int out_size) {
    const float* x      = (const float*)d_in[0];
    const float* n1w    = (const float*)d_in[1];
    const float* n1b    = (const float*)d_in[2];
    const float* kvq_w  = (const float*)d_in[3];
    const float* kvq_b  = (const float*)d_in[4];
    const float* proj_w = (const float*)d_in[5];
    const float* proj_b = (const float*)d_in[6];
    const float* n2w    = (const float*)d_in[7];
    const float* n2b    = (const float*)d_in[8];
    const float* fc1_w  = (const float*)d_in[9];
    const float* fc1_b  = (const float*)d_in[10];
    const float* fc2_w  = (const float*)d_in[11];
    const float* fc2_b  = (const float*)d_in[12];
    float* out = (float*)d_out;

    static bool attrs_set = false;
    if (!attrs_set) {
        cudaFuncSetAttribute(kvqattn_kernel,            cudaFuncAttributeMaxDynamicSharedMemorySize, KV_SMEM);
        cudaFuncSetAttribute(gemm_kernel<2, 1024, 256>, cudaFuncAttributeMaxDynamicSharedMemorySize, GEMM_SMEM);
        cudaFuncSetAttribute(gemm_kernel<3, 256, 1024>, cudaFuncAttributeMaxDynamicSharedMemorySize, GEMM_SMEM);
        cudaFuncSetAttribute(projln_kernel,             cudaFuncAttributeMaxDynamicSharedMemorySize, PROJ_SMEM);
        attrs_set = true;
    }

    prep_kernel<<<LN1_BLOCKS + CONV_BLOCKS, 256>>>(x, n1w, n1b, kvq_w, kvq_b,
                                                   proj_w, fc1_w, fc2_w);
    kvqattn_kernel<<<dim3(8, MROWS / KBM), 256, KV_SMEM>>>();
    projln_kernel<<<MROWS / PBM, 256, PROJ_SMEM>>>(proj_b, x, n2w, n2b);
    gemm_kernel<2, 1024, 256><<<dim3(8, MROWS / BM), 256, GEMM_SMEM>>>(fc1_b, nullptr);
    gemm_kernel<3, 256, 1024><<<dim3(2, MROWS / BM), 256, GEMM_SMEM>>>(fc2_b, out);
}

// round 16
// speedup vs baseline: 1.0214x; 1.0214x over previous
#include <cuda_runtime.h>
#include <cuda_fp16.h>
#include <cstdint>
#include <math.h>

typedef __half f16;

#define BDIM 48
#define HDIM 56
#define WDIM 56
#define CDIM 256
#define TDIM 3
#define NTOK 50176        /* (B/T)*H*W */
#define MROWS 150528      /* NTOK*T = B*H*W */
#define HID 1024
#define EPSLN 1e-6f

// ---------------- scratch (static device allocations) ----------------
__device__ f16   g_xn  [(size_t)MROWS*CDIM];
__device__ f16   g_attn[(size_t)MROWS*CDIM];
__device__ f16   g_xt16[(size_t)MROWS*CDIM];   /* xt = proj_out + bias + x, fp16 */
__device__ f16   g_xtn [(size_t)MROWS*CDIM];
__device__ f16   g_h   [(size_t)MROWS*HID];
__device__ f16   g_wkvq[3*CDIM*CDIM];          /* head-grouped permuted rows */
__device__ float g_bkvq[3*CDIM];               /* permuted kvq bias */
__device__ f16   g_wproj[CDIM*CDIM];
__device__ f16   g_wfc1[HID*CDIM];
__device__ f16   g_wfc2[CDIM*HID];

// ---------------- small helpers ----------------
__device__ __forceinline__ uint32_t pack_h2(float a, float b) {
    __half2 h = __floats2half2_rn(a, b);
    return *reinterpret_cast<uint32_t*>(&h);
}
__device__ __forceinline__ float2 unpack_h2(uint32_t u) {
    return __half22float2(*reinterpret_cast<__half2*>(&u));
}
__device__ __forceinline__ uint32_t s2u(const void* p) {
    uint32_t a;
    asm("{ .reg .u64 t; cvta.to.shared.u64 t, %1; cvt.u32.u64 %0, t; }" : "=r"(a) : "l"(p));
    return a;
}
#define CP_ASYNC16(saddr, gptr) \
    asm volatile("cp.async.cg.shared.global [%0], [%1], 16;" :: "r"(saddr), "l"(gptr) : "memory")
#define CP_COMMIT() asm volatile("cp.async.commit_group;" ::: "memory")

#define LDSM_X4(r0, r1, r2, r3, a) \
    asm volatile("ldmatrix.sync.aligned.m8n8.x4.shared.b16 {%0,%1,%2,%3}, [%4];" \
        : "=r"(r0), "=r"(r1), "=r"(r2), "=r"(r3) : "r"(a))

#define HMMA_F16(acc, a0, a1, a2, a3, b0, b1) \
    asm volatile( \
        "mma.sync.aligned.m16n8k16.row.col.f16.f16.f16.f16 " \
        "{%0,%1}, {%2,%3,%4,%5}, {%6,%7}, {%0,%1};\n" \
        : "+r"((acc)[0]), "+r"((acc)[1]) \
        : "r"(a0), "r"(a1), "r"(a2), "r"(a3), "r"(b0), "r"(b1))

// ---------------- LN1 + weight conversion (merged, grid-partitioned) ----------
#define LN1_BLOCKS (MROWS / 8)       /* 18816 */
#define CONV_BLOCKS 1024

__device__ __forceinline__ void warpLN8(float* v, float& mu, float& rstd) {
    float s = 0.f, s2 = 0.f;
    #pragma unroll
    for (int j = 0; j < 8; j++) { s += v[j]; s2 += v[j] * v[j]; }
    #pragma unroll
    for (int o = 16; o; o >>= 1) {
        s  += __shfl_xor_sync(0xffffffffu, s,  o);
        s2 += __shfl_xor_sync(0xffffffffu, s2, o);
    }
    mu = s * (1.f / CDIM);
    rstd = rsqrtf(s2 * (1.f / CDIM) - mu * mu + EPSLN);
}

__global__ void prep_kernel(const float* __restrict__ x, const float* __restrict__ w,
                            const float* __restrict__ b,
                            const float* __restrict__ wkvq, const float* __restrict__ kvq_b,
                            const float* __restrict__ wproj,
                            const float* __restrict__ wfc1, const float* __restrict__ wfc2) {
    if (blockIdx.x >= LN1_BLOCKS) {
        int i = (blockIdx.x - LN1_BLOCKS) * 256 + threadIdx.x;
        if (i < 3*CDIM*CDIM) {
            int rp = i >> 8, k = i & 255;
            int h = rp / 96, j = rp - h * 96;
            int orig = (j < 32) ? (h*32 + j) : (j < 64) ? (256 + h*32 + j - 32) : (512 + h*32 + j - 64);
            g_wkvq[i] = __float2half(wkvq[orig * 256 + k]);
            if (i < 768) {
                int hh = i / 96, jj = i - hh * 96;
                int ob = (jj < 32) ? (hh*32 + jj) : (jj < 64) ? (256 + hh*32 + jj - 32) : (512 + hh*32 + jj - 64);
                g_bkvq[i] = kvq_b[ob];
            }
        }
        if (i < CDIM*CDIM)   g_wproj[i] = __float2half(wproj[i]);
        if (i < HID*CDIM) {
            g_wfc1[i] = __float2half(wfc1[i]);
            g_wfc2[i] = __float2half(wfc2[i]);
        }
        return;
    }
    int r = blockIdx.x * 8 + (threadIdx.x >> 5);
    int lane = threadIdx.x & 31;
    const float4* px = (const float4*)(x + (size_t)r * CDIM);
    float4 a0 = px[lane * 2], a1 = px[lane * 2 + 1];
    float v[8] = {a0.x, a0.y, a0.z, a0.w, a1.x, a1.y, a1.z, a1.w};
    float mu, rstd;
    warpLN8(v, mu, rstd);
    float4 w0 = ((const float4*)w)[lane*2], w1 = ((const float4*)w)[lane*2+1];
    float4 b0 = ((const float4*)b)[lane*2], b1 = ((const float4*)b)[lane*2+1];
    float wv[8] = {w0.x,w0.y,w0.z,w0.w,w1.x,w1.y,w1.z,w1.w};
    float bv[8] = {b0.x,b0.y,b0.z,b0.w,b1.x,b1.y,b1.z,b1.w};
    uint32_t o[4];
    #pragma unroll
    for (int j = 0; j < 4; j++) {
        float y0 = (v[2*j]   - mu) * rstd * wv[2*j]   + bv[2*j];
        float y1 = (v[2*j+1] - mu) * rstd * wv[2*j+1] + bv[2*j+1];
        o[j] = pack_h2(y0, y1);
    }
    int ww = r % WDIM; int r2 = r / WDIM;
    int hh = r2 % HDIM; int bb = r2 / HDIM;
    int bh = bb / TDIM, t = bb - bh * TDIM;
    int m = ((bh * HDIM + hh) * WDIM + ww) * TDIM + t;
    ((uint4*)(g_xn + (size_t)m * CDIM))[lane] = make_uint4(o[0], o[1], o[2], o[3]);
}

// ======= fused kvq GEMM + attention: 192x96 tile, 4-stage ring (R14 config) =======
#define KBM 192
#define KBN 96
#define BKK 32
#define LDSS 40
#define S4 4
#define KA_BYTES (KBM * LDSS * 2)      /* 15360 */
#define KB_BYTES (KBN * LDSS * 2)      /* 7680  */
#define KSTAGE (KA_BYTES + KB_BYTES)   /* 23040 */
#define KV_SMEM (S4 * KSTAGE)          /* 92160 */
#define ATTP 104                        /* attention smem pitch (halves) */

__global__ void __launch_bounds__(256, 2) kvqattn_kernel() {
    constexpr int NKT = CDIM / BKK;    // 8
    extern __shared__ char dsm[];
    const uint32_t p0 = s2u(dsm);

    const int bn = blockIdx.x, bm = blockIdx.y;   // bn = head
    const int tid = threadIdx.x;
    const int warp = tid >> 5, lane = tid & 31;
    const int wm = warp & 3, wn = warp >> 2;      // 4(m) x 2(n); warp tile 48x48
    const int gro = lane >> 2, thr = lane & 3;
    const size_t aBase = (size_t)bm * KBM * CDIM;
    const size_t bBase = (size_t)bn * KBN * CDIM;

    const int aRow = wm * 48 + (lane & 7) + ((lane >> 3) & 1) * 8;  // + mi*16
    const int aCol = (lane >> 4) * 8;
    const int bRow = wn * 48 + (lane & 7) + (lane >> 4) * 8;        // + pr*16
    const int bCol = ((lane >> 3) & 1) * 8;

    auto loadTile = [&](int st, int kt) {
        int k0 = kt * BKK;
        uint32_t base = p0 + st * KSTAGE;
        #pragma unroll
        for (int i = 0; i < 3; i++) {          // A: 192x4 = 768 chunks
            int idx = tid + i * 256;
            int row = idx >> 2, ch = idx & 3;
            CP_ASYNC16(base + (uint32_t)((row * LDSS + ch * 8) * 2),
                       g_xn + aBase + (size_t)row * CDIM + k0 + ch * 8);
        }
        {                                       // B: 96x4 = 384 chunks
            uint32_t bB = base + KA_BYTES;
            int row = tid >> 2, ch = tid & 3;
            CP_ASYNC16(bB + (uint32_t)((row * LDSS + ch * 8) * 2),
                       g_wkvq + bBase + (size_t)row * CDIM + k0 + ch * 8);
            if (tid < 128) {
                int idx = 256 + tid;
                int r2 = idx >> 2, c2 = idx & 3;
                CP_ASYNC16(bB + (uint32_t)((r2 * LDSS + c2 * 8) * 2),
                           g_wkvq + bBase + (size_t)r2 * CDIM + k0 + c2 * 8);
            }
        }
        CP_COMMIT();
    };

    uint32_t acch[3][6][2];
    #pragma unroll
    for (int i = 0; i < 3; i++)
        #pragma unroll
        for (int j = 0; j < 6; j++) { acch[i][j][0] = 0u; acch[i][j][1] = 0u; }

    #pragma unroll
    for (int s = 0; s < S4 - 1; s++) loadTile(s, s);

    #pragma unroll
    for (int kt = 0; kt < NKT; kt++) {
        if (kt < NKT - 2)       asm volatile("cp.async.wait_group 2;" ::: "memory");
        else if (kt == NKT - 2) asm volatile("cp.async.wait_group 1;" ::: "memory");
        else                    asm volatile("cp.async.wait_group 0;" ::: "memory");
        __syncthreads();
        if (kt + S4 - 1 < NKT) loadTile((kt + S4 - 1) & (S4 - 1), kt + S4 - 1);
        const int st = kt & (S4 - 1);
        uint32_t base = p0 + st * KSTAGE;
        #pragma unroll
        for (int ks = 0; ks < 2; ks++) {
            uint32_t af[3][4];
            #pragma unroll
            for (int mi = 0; mi < 3; mi++) {
                uint32_t addr = base +
                    (uint32_t)(((aRow + mi * 16) * LDSS + ks * 16 + aCol) * 2);
                LDSM_X4(af[mi][0], af[mi][1], af[mi][2], af[mi][3], addr);
            }
            uint32_t bfr[6][2];
            #pragma unroll
            for (int pr = 0; pr < 3; pr++) {
                uint32_t addr = base + KA_BYTES +
                    (uint32_t)(((bRow + pr * 16) * LDSS + ks * 16 + bCol) * 2);
                LDSM_X4(bfr[pr*2][0], bfr[pr*2][1], bfr[pr*2+1][0], bfr[pr*2+1][1], addr);
            }
            #pragma unroll
            for (int ni = 0; ni < 6; ni++)
                #pragma unroll
                for (int mi = 0; mi < 3; mi++)
                    HMMA_F16(acch[mi][ni], af[mi][0], af[mi][1], af[mi][2], af[mi][3],
                             bfr[ni][0], bfr[ni][1]);
        }
    }

    // ---- epilogue 1: biased kvq tile -> smem (192 rows x 96 cols, pitch 104) ----
    __syncthreads();   // all MMAs done reading pipeline smem
    f16* att = (f16*)dsm;
    #pragma unroll
    for (int mi = 0; mi < 3; mi++) {
        #pragma unroll
        for (int rr = 0; rr < 2; rr++) {
            int row = wm * 48 + mi * 16 + rr * 8 + gro;
            #pragma unroll
            for (int ni = 0; ni < 6; ni++) {
                int j = wn * 48 + ni * 8 + thr * 2;
                float2 d = unpack_h2(acch[mi][ni][rr]);
                float2 bb = *(const float2*)&g_bkvq[bn * 96 + j];
                *(uint32_t*)&att[row * ATTP + j] = pack_h2(d.x + bb.x, d.y + bb.y);
            }
        }
    }
    __syncthreads();

    // ---- epilogue 2: attention; 4 threads per n-group, 8 d-channels each ----
    {
        int g = tid >> 2, qd = tid & 3;       // 64 groups, quarter qd
        const f16* rbase = att + (3 * g) * ATTP + qd * 8;
        float2 kv[3][4], qv[3][4];
        #pragma unroll
        for (int t = 0; t < 3; t++) {
            uint4 uk = *(const uint4*)(rbase + t * ATTP +  0);
            uint4 uq = *(const uint4*)(rbase + t * ATTP + 64);
            kv[t][0] = unpack_h2(uk.x); kv[t][1] = unpack_h2(uk.y);
            kv[t][2] = unpack_h2(uk.z); kv[t][3] = unpack_h2(uk.w);
            qv[t][0] = unpack_h2(uq.x); qv[t][1] = unpack_h2(uq.y);
            qv[t][2] = unpack_h2(uq.z); qv[t][3] = unpack_h2(uq.w);
        }
        float dot[3][3];
        #pragma unroll
        for (int a = 0; a < 3; a++)
            #pragma unroll
            for (int s = 0; s < 3; s++) {
                float p = 0.f;
                #pragma unroll
                for (int j = 0; j < 4; j++)
                    p += qv[a][j].x * kv[s][j].x + qv[a][j].y * kv[s][j].y;
                dot[a][s] = p;
            }
        #pragma unroll
        for (int a = 0; a < 3; a++)
            #pragma unroll
            for (int s = 0; s < 3; s++) {
                dot[a][s] += __shfl_xor_sync(0xffffffffu, dot[a][s], 1);
                dot[a][s] += __shfl_xor_sync(0xffffffffu, dot[a][s], 2);
            }
        float wgt[3][3];
        #pragma unroll
        for (int a = 0; a < 3; a++) {
            float l0 = dot[a][0] * 0.17677669529663687f;
            float l1 = dot[a][1] * 0.17677669529663687f;
            float l2 = dot[a][2] * 0.17677669529663687f;
            float mx = fmaxf(l0, fmaxf(l1, l2));
            float e0 = __expf(l0 - mx), e1 = __expf(l1 - mx), e2 = __expf(l2 - mx);
            float inv = 1.f / (e0 + e1 + e2);
            wgt[a][0] = e0 * inv; wgt[a][1] = e1 * inv; wgt[a][2] = e2 * inv;
        }
        float2 vv[3][4];
        #pragma unroll
        for (int t = 0; t < 3; t++) {
            uint4 uv = *(const uint4*)(rbase + t * ATTP + 32);
            vv[t][0] = unpack_h2(uv.x); vv[t][1] = unpack_h2(uv.y);
            vv[t][2] = unpack_h2(uv.z); vv[t][3] = unpack_h2(uv.w);
        }
        int n = bm * 64 + g;
        #pragma unroll
        for (int a = 0; a < 3; a++) {
            uint32_t o[4];
            #pragma unroll
            for (int j = 0; j < 4; j++) {
                float ox = wgt[a][0]*vv[0][j].x + wgt[a][1]*vv[1][j].x + wgt[a][2]*vv[2][j].x;
                float oy = wgt[a][0]*vv[0][j].y + wgt[a][1]*vv[1][j].y + wgt[a][2]*vv[2][j].y;
                o[j] = pack_h2(ox, oy);
            }
            *(uint4*)(g_attn + (size_t)(n*3 + a) * CDIM + bn*32 + qd*8) =
                make_uint4(o[0], o[1], o[2], o[3]);
        }
    }
}

// ====== main GEMM: 128x128 tile, 3-stage ring, 3 CTAs/SM, fully unrolled ======
#define BM 128
#define BN 128
#define GS 3
#define STAGE_BYTES (BM * LDSS * 2)                 /* 10240 */
#define GEMM_SMEM (GS * 2 * STAGE_BYTES)            /* 61440 */

// EPI: 2 = fc1 (f16 acc, bias + gelu -> f16 g_h)
//      3 = fc2 (f16 acc, bias + xt16 residual -> fp32 out, scattered)
template<int EPI, int NDIM, int KDIM>
__global__ void __launch_bounds__(256, 3) gemm_kernel(const float* __restrict__ bias,
                                                      float* __restrict__ gout) {
    constexpr int NKT = KDIM / BKK;
    const f16 *A, *W;
    if constexpr (EPI == 2) { A = g_xtn; W = g_wfc1; }
    else                    { A = g_h;   W = g_wfc2; }

    extern __shared__ char dsm[];
    const uint32_t sA0 = s2u(dsm);
    const uint32_t sB0 = sA0 + GS * STAGE_BYTES;

    const int bn = blockIdx.x, bm = blockIdx.y;
    const int tid = threadIdx.x;
    const int warp = tid >> 5, lane = tid & 31;
    const int wm = warp & 3, wn = warp >> 2;
    const int gro = lane >> 2, thr = lane & 3;
    const size_t aBase = (size_t)bm * BM * KDIM;
    const size_t bBase = (size_t)bn * BN * KDIM;

    const int aRow = wm * 32 + (lane & 7) + ((lane >> 3) & 1) * 8;
    const int aCol = (lane >> 4) * 8;
    const int bRow = wn * 64 + (lane & 7) + (lane >> 4) * 8;
    const int bCol = ((lane >> 3) & 1) * 8;

    const int lrow = tid >> 2, lch = tid & 3;
    auto loadTile = [&](int st, int kt) {
        int k0 = kt * BKK;
        uint32_t dA = sA0 + st * STAGE_BYTES + (uint32_t)((lrow * LDSS + lch * 8) * 2);
        uint32_t dB = sB0 + st * STAGE_BYTES + (uint32_t)((lrow * LDSS + lch * 8) * 2);
        const f16* ga = A + aBase + (size_t)lrow * KDIM + k0 + lch * 8;
        const f16* gb = W + bBase + (size_t)lrow * KDIM + k0 + lch * 8;
        CP_ASYNC16(dA, ga);
        CP_ASYNC16(dA + (uint32_t)(64 * LDSS * 2), ga + (size_t)64 * KDIM);
        CP_ASYNC16(dB, gb);
        CP_ASYNC16(dB + (uint32_t)(64 * LDSS * 2), gb + (size_t)64 * KDIM);
        CP_COMMIT();
    };

    uint32_t acch[2][8][2];
    #pragma unroll
    for (int i = 0; i < 2; i++)
        #pragma unroll
        for (int j = 0; j < 8; j++) { acch[i][j][0] = 0u; acch[i][j][1] = 0u; }

    loadTile(0, 0);
    loadTile(1, 1);
    #pragma unroll
    for (int kt = 0; kt < NKT; kt++) {
        if (kt < NKT - 1) asm volatile("cp.async.wait_group 1;" ::: "memory");
        else              asm volatile("cp.async.wait_group 0;" ::: "memory");
        __syncthreads();
        if (kt + 2 < NKT) loadTile((kt + 2) % GS, kt + 2);
        const int st = kt % GS;
        #pragma unroll
        for (int ks = 0; ks < 2; ks++) {
            uint32_t af[2][4];
            #pragma unroll
            for (int mi = 0; mi < 2; mi++) {
                uint32_t addr = sA0 + st * STAGE_BYTES +
                    (uint32_t)(((aRow + mi * 16) * LDSS + ks * 16 + aCol) * 2);
                LDSM_X4(af[mi][0], af[mi][1], af[mi][2], af[mi][3], addr);
            }
            uint32_t bfr[8][2];
            #pragma unroll
            for (int pr = 0; pr < 4; pr++) {
                uint32_t addr = sB0 + st * STAGE_BYTES +
                    (uint32_t)(((bRow + pr * 16) * LDSS + ks * 16 + bCol) * 2);
                LDSM_X4(bfr[pr*2][0], bfr[pr*2][1], bfr[pr*2+1][0], bfr[pr*2+1][1], addr);
            }
            #pragma unroll
            for (int ni = 0; ni < 8; ni++)
                #pragma unroll
                for (int mi = 0; mi < 2; mi++)
                    HMMA_F16(acch[mi][ni], af[mi][0], af[mi][1], af[mi][2], af[mi][3],
                             bfr[ni][0], bfr[ni][1]);
        }
    }

    // ---- epilogue ----
    const int cb = bn * BN + wn * 64 + thr * 2;
    #pragma unroll
    for (int mi = 0; mi < 2; mi++) {
        #pragma unroll
        for (int rr = 0; rr < 2; rr++) {
            int m = bm * BM + wm * 32 + mi * 16 + rr * 8 + gro;
            size_t xidx = 0;
            if constexpr (EPI == 3) {
                int t = m % 3;
                int n = m / 3;
                int ww = n % WDIM;
                int r2 = n / WDIM;
                int hh = r2 % HDIM;
                int bhat = r2 / HDIM;
                int b = bhat * TDIM + t;
                xidx = ((size_t)((b * HDIM + hh) * WDIM + ww)) * CDIM;
            }
            #pragma unroll
            for (int ni = 0; ni < 8; ni++) {
                int c = cb + ni * 8;
                float2 d = unpack_h2(acch[mi][ni][rr]);
                float v0 = d.x + bias[c], v1 = d.y + bias[c + 1];
                if constexpr (EPI == 2) {
                    v0 = 0.5f * v0 * (1.f + erff(v0 * 0.7071067811865475f));
                    v1 = 0.5f * v1 * (1.f + erff(v1 * 0.7071067811865475f));
                    *(uint32_t*)&g_h[(size_t)m * NDIM + c] = pack_h2(v0, v1);
                } else {
                    float2 xt = unpack_h2(*(const uint32_t*)&g_xt16[(size_t)m * CDIM + c]);
                    *(float2*)&gout[xidx + c] = make_float2(v0 + xt.x, v1 + xt.y);
                }
            }
        }
    }
}

// ====== fused proj + residual + LN2: 128x256 tile, warp 64x64, 3-stage, unrolled ======
#define PBM 128
#define PS 3
#define PA_BYTES (PBM * LDSS * 2)     /* 10240 */
#define PB_BYTES (CDIM * LDSS * 2)    /* 20480 */
#define PSTAGE (PA_BYTES + PB_BYTES)  /* 30720 */
#define PROJ_SMEM (PS * PSTAGE)       /* 92160 */

__global__ void __launch_bounds__(256, 2) projln_kernel(const float* __restrict__ bias,
                                                        const float* __restrict__ x,
                                                        const float* __restrict__ w2,
                                                        const float* __restrict__ b2) {
    constexpr int NKT = CDIM / BKK;   // 8
    extern __shared__ char dsm[];
    __shared__ float2 red[PBM][4];

    const uint32_t p0 = s2u(dsm);
    const int bm = blockIdx.x;
    const int tid = threadIdx.x;
    const int warp = tid >> 5, lane = tid & 31;
    const int wm = warp & 1, wn = warp >> 1;      // 2(m) x 4(n); warp tile 64x64
    const int gro = lane >> 2, thr = lane & 3;
    const size_t aBase = (size_t)bm * PBM * CDIM;

    const int aRow = wm * 64 + (lane & 7) + ((lane >> 3) & 1) * 8;   // + mi*16
    const int aCol = (lane >> 4) * 8;
    const int bRow = wn * 64 + (lane & 7) + (lane >> 4) * 8;         // + pr*16
    const int bCol = ((lane >> 3) & 1) * 8;

    auto loadTile = [&](int st, int kt) {
        int k0 = kt * BKK;
        uint32_t base = p0 + st * PSTAGE;
        #pragma unroll
        for (int i = 0; i < 2; i++) {    // A: 128x4 = 512 chunks, 2/thread
            int idx = tid + i * 256;
            int row = idx >> 2, ch = idx & 3;
            CP_ASYNC16(base + (uint32_t)((row * LDSS + ch * 8) * 2),
                       g_attn + aBase + (size_t)row * CDIM + k0 + ch * 8);
        }
        {
            uint32_t bB = base + PA_BYTES;
            #pragma unroll
            for (int i = 0; i < 4; i++) {   // B: 256x4 = 1024 chunks, 4/thread
                int idx = tid + i * 256;
                int row = idx >> 2, ch = idx & 3;
                CP_ASYNC16(bB + (uint32_t)((row * LDSS + ch * 8) * 2),
                           g_wproj + (size_t)row * CDIM + k0 + ch * 8);
            }
        }
        CP_COMMIT();
    };

    uint32_t acch[4][8][2];
    #pragma unroll
    for (int i = 0; i < 4; i++)
        #pragma unroll
        for (int j = 0; j < 8; j++) { acch[i][j][0] = 0u; acch[i][j][1] = 0u; }

    loadTile(0, 0);
    loadTile(1, 1);
    #pragma unroll
    for (int kt = 0; kt < NKT; kt++) {
        if (kt < NKT - 1) asm volatile("cp.async.wait_group 1;" ::: "memory");
        else              asm volatile("cp.async.wait_group 0;" ::: "memory");
        __syncthreads();
        if (kt + 2 < NKT) loadTile((kt + 2) % PS, kt + 2);
        const int st = kt % PS;
        uint32_t base = p0 + st * PSTAGE;
        #pragma unroll
        for (int ks = 0; ks < 2; ks++) {
            uint32_t af[4][4];
            #pragma unroll
            for (int mi = 0; mi < 4; mi++) {
                uint32_t addr = base +
                    (uint32_t)(((aRow + mi * 16) * LDSS + ks * 16 + aCol) * 2);
                LDSM_X4(af[mi][0], af[mi][1], af[mi][2], af[mi][3], addr);
            }
            uint32_t bfr[8][2];
            #pragma unroll
            for (int pr = 0; pr < 4; pr++) {
                uint32_t addr = base + PA_BYTES +
                    (uint32_t)(((bRow + pr * 16) * LDSS + ks * 16 + bCol) * 2);
                LDSM_X4(bfr[pr*2][0], bfr[pr*2][1], bfr[pr*2+1][0], bfr[pr*2+1][1], addr);
            }
            #pragma unroll
            for (int ni = 0; ni < 8; ni++)
                #pragma unroll
                for (int mi = 0; mi < 4; mi++)
                    HMMA_F16(acch[mi][ni], af[mi][0], af[mi][1], af[mi][2], af[mi][3],
                             bfr[ni][0], bfr[ni][1]);
        }
    }

    // ---- epilogue pass 1: bias + x -> xt (f16 gmem + regs); row stats ----
    #pragma unroll
    for (int mi = 0; mi < 4; mi++) {
        #pragma unroll
        for (int rr = 0; rr < 2; rr++) {
            int ml = wm * 64 + mi * 16 + rr * 8 + gro;
            int m = bm * PBM + ml;
            int t = m % 3;
            int n = m / 3;
            int ww = n % WDIM;
            int r2 = n / WDIM;
            int hh = r2 % HDIM;
            int bhat = r2 / HDIM;
            const float* xrow = x + ((size_t)(((bhat * TDIM + t) * HDIM + hh) * WDIM + ww)) * CDIM;

            float s = 0.f, s2 = 0.f;
            #pragma unroll
            for (int ni = 0; ni < 8; ni++) {
                int c = wn * 64 + ni * 8 + thr * 2;
                float2 d = unpack_h2(acch[mi][ni][rr]);
                float2 bb = *(const float2*)&bias[c];
                float2 xx = *(const float2*)&xrow[c];
                float v0 = d.x + bb.x + xx.x;
                float v1 = d.y + bb.y + xx.y;
                uint32_t pk = pack_h2(v0, v1);
                *(uint32_t*)&g_xt16[(size_t)m * CDIM + c] = pk;
                acch[mi][ni][rr] = pk;                 // xt stays in regs
                s += v0 + v1; s2 += v0*v0 + v1*v1;
            }
            #pragma unroll
            for (int o = 1; o < 4; o <<= 1) {
                s  += __shfl_xor_sync(0xffffffffu, s,  o);
                s2 += __shfl_xor_sync(0xffffffffu, s2, o);
            }
            if (thr == 0) red[ml][wn] = make_float2(s, s2);
        }
    }
    __syncthreads();

    // ---- epilogue pass 2: normalize from regs -> g_xtn ----
    #pragma unroll
    for (int mi = 0; mi < 4; mi++) {
        #pragma unroll
        for (int rr = 0; rr < 2; rr++) {
            int ml = wm * 64 + mi * 16 + rr * 8 + gro;
            int m = bm * PBM + ml;
            float2 r0 = red[ml][0], r1 = red[ml][1], r2v = red[ml][2], r3 = red[ml][3];
            float mu = (r0.x + r1.x + r2v.x + r3.x) * (1.f / CDIM);
            float var = (r0.y + r1.y + r2v.y + r3.y) * (1.f / CDIM) - mu * mu;
            float rstd = rsqrtf(var + EPSLN);
            #pragma unroll
            for (int ni = 0; ni < 8; ni++) {
                int c = wn * 64 + ni * 8 + thr * 2;
                float2 vt = unpack_h2(acch[mi][ni][rr]);
                float2 ww2 = *(const float2*)&w2[c];
                float2 bb2 = *(const float2*)&b2[c];
                float y0 = (vt.x - mu) * rstd * ww2.x + bb2.x;
                float y1 = (vt.y - mu) * rstd * ww2.y + bb2.y;
                *(uint32_t*)&g_xtn[(size_t)m * CDIM + c] = pack_h2(y0, y1);
            }
        }
    }
}

// ---------------- launch ----------------
extern "C" void kernel_launch(void* const* d_in, const int* in_sizes, int n_in,
                              void* d_out, int out_size) {
    const float* x      = (const float*)d_in[0];
    const float* n1w    = (const float*)d_in[1];
    const float* n1b    = (const float*)d_in[2];
    const float* kvq_w  = (const float*)d_in[3];
    const float* kvq_b  = (const float*)d_in[4];
    const float* proj_w = (const float*)d_in[5];
    const float* proj_b = (const float*)d_in[6];
    const float* n2w    = (const float*)d_in[7];
    const float* n2b    = (const float*)d_in[8];
    const float* fc1_w  = (const float*)d_in[9];
    const float* fc1_b  = (const float*)d_in[10];
    const float* fc2_w  = (const float*)d_in[11];
    const float* fc2_b  = (const float*)d_in[12];
    float* out = (float*)d_out;

    static bool attrs_set = false;
    if (!attrs_set) {
        cudaFuncSetAttribute(kvqattn_kernel,            cudaFuncAttributeMaxDynamicSharedMemorySize, KV_SMEM);
        cudaFuncSetAttribute(gemm_kernel<2, 1024, 256>, cudaFuncAttributeMaxDynamicSharedMemorySize, GEMM_SMEM);
        cudaFuncSetAttribute(gemm_kernel<3, 256, 1024>, cudaFuncAttributeMaxDynamicSharedMemorySize, GEMM_SMEM);
        cudaFuncSetAttribute(projln_kernel,             cudaFuncAttributeMaxDynamicSharedMemorySize, PROJ_SMEM);
        attrs_set = true;
    }

    prep_kernel<<<LN1_BLOCKS + CONV_BLOCKS, 256>>>(x, n1w, n1b, kvq_w, kvq_b,
                                                   proj_w, fc1_w, fc2_w);
    kvqattn_kernel<<<dim3(8, MROWS / KBM), 256, KV_SMEM>>>();
    projln_kernel<<<MROWS / PBM, 256, PROJ_SMEM>>>(proj_b, x, n2w, n2b);
    gemm_kernel<2, 1024, 256><<<dim3(8, MROWS / BM), 256, GEMM_SMEM>>>(fc1_b, nullptr);
    gemm_kernel<3, 256, 1024><<<dim3(2, MROWS / BM), 256, GEMM_SMEM>>>(fc2_b, out);
}